// round 5
// baseline (speedup 1.0000x reference)
#include <cuda_runtime.h>

#define CDIM 128
#define HDIM 64
#define EDIM 16
#define N_MAX 50000

// Scratch:
// g_s[n*64 + k]        = (h @ W1^T)[n][k] + att_b[k]
// g_th[n*128 + p*4+..] = interleaved {t0,t1,h0,h1} per k-pair p=k/2:
//                        t = (h @ W2^T)[n][k], h = (x @ fc_w^T + fc_b)[n][k]
__device__ float g_s [N_MAX * HDIM];
__device__ float g_th[N_MAX * HDIM * 2];

// ---------------------------------------------------------------------------
// Node kernel: tile of 128 nodes per block, 256 threads.
// Thread tile: 4 nodes x 8 k-outputs (32 accumulators).
// Stage 1: h = x @ fc_w^T + fc_b  (K=128, chunks of 16) -> kept in smem hT
// Stage 2: s = h @ W1^T + att_b ; t = h @ W2^T  (K=64)
// Writes g_s and interleaved g_th; zeroes `out` (harness poisons with 0xAA).
// ---------------------------------------------------------------------------
__global__ __launch_bounds__(256) void node_kernel(
    const float* __restrict__ x,
    const float* __restrict__ fc_w,
    const float* __restrict__ fc_b,
    const float* __restrict__ att_w,
    const float* __restrict__ att_b,
    float* __restrict__ out,
    int N)
{
    __shared__ float hT[64 * 132];     // hT[c][n] = h[n][c], padded rows
    __shared__ float a_sm[16 * 132];   // x chunk, transposed: a_sm[c][n]
    __shared__ float b_sm[16 * 68];    // weight chunk, transposed: b_sm[c][k]

    const int t     = threadIdx.x;
    const int tn    = t & 31;
    const int tk    = t >> 5;
    const int kb    = tk * 8;
    const int node0 = blockIdx.x * 128;

    float acc[4][8];

    // ---------------- Stage 1: h ----------------
    {
        float bias[8];
#pragma unroll
        for (int j = 0; j < 8; j++) bias[j] = __ldg(&fc_b[kb + j]);
#pragma unroll
        for (int i = 0; i < 4; i++)
#pragma unroll
            for (int j = 0; j < 8; j++) acc[i][j] = bias[j];

        for (int cb = 0; cb < 8; cb++) {
#pragma unroll
            for (int j = 0; j < 8; j++) {
                int idx = t + j * 256;
                int n = idx >> 4, c = idx & 15;
                int gn = node0 + n;
                float v = (gn < N) ? x[gn * CDIM + cb * 16 + c] : 0.0f;
                a_sm[c * 132 + n] = v;
            }
#pragma unroll
            for (int j = 0; j < 4; j++) {
                int idx = t + j * 256;
                int k = idx >> 4, c = idx & 15;
                b_sm[c * 68 + k] = fc_w[k * CDIM + cb * 16 + c];
            }
            __syncthreads();
#pragma unroll
            for (int c = 0; c < 16; c++) {
                float4 av  = *(const float4*)&a_sm[c * 132 + tn * 4];
                float4 bv0 = *(const float4*)&b_sm[c * 68 + kb];
                float4 bv1 = *(const float4*)&b_sm[c * 68 + kb + 4];
                float aa[4] = {av.x, av.y, av.z, av.w};
                float bb[8] = {bv0.x, bv0.y, bv0.z, bv0.w,
                               bv1.x, bv1.y, bv1.z, bv1.w};
#pragma unroll
                for (int i = 0; i < 4; i++)
#pragma unroll
                    for (int j = 0; j < 8; j++)
                        acc[i][j] = fmaf(aa[i], bb[j], acc[i][j]);
            }
            __syncthreads();
        }

        // Stash transposed h in smem; zero `out` rows.
#pragma unroll
        for (int i = 0; i < 4; i++) {
            int gn = node0 + tn * 4 + i;
            if (gn < N) {
                float4 z = make_float4(0.f, 0.f, 0.f, 0.f);
                *(float4*)&out[(size_t)gn * HDIM + kb]     = z;
                *(float4*)&out[(size_t)gn * HDIM + kb + 4] = z;
            }
#pragma unroll
            for (int j = 0; j < 8; j++)
                hT[(kb + j) * 132 + tn * 4 + i] = acc[i][j];
        }
        __syncthreads();
    }

    // ---------------- Stage 2: s (p=0) and t (p=1) ----------------
    for (int p = 0; p < 2; p++) {
        float bias[8];
#pragma unroll
        for (int j = 0; j < 8; j++)
            bias[j] = (p == 0) ? __ldg(&att_b[kb + j]) : 0.0f;
#pragma unroll
        for (int i = 0; i < 4; i++)
#pragma unroll
            for (int j = 0; j < 8; j++) acc[i][j] = bias[j];

        for (int cb = 0; cb < 4; cb++) {
#pragma unroll
            for (int j = 0; j < 4; j++) {
                int idx = t + j * 256;
                int k = idx >> 4, c = idx & 15;
                b_sm[c * 68 + k] = att_w[k * (2 * HDIM + EDIM) + p * 64 + cb * 16 + c];
            }
            __syncthreads();
#pragma unroll
            for (int c16 = 0; c16 < 16; c16++) {
                int c = cb * 16 + c16;
                float4 av  = *(const float4*)&hT[c * 132 + tn * 4];
                float4 bv0 = *(const float4*)&b_sm[c16 * 68 + kb];
                float4 bv1 = *(const float4*)&b_sm[c16 * 68 + kb + 4];
                float aa[4] = {av.x, av.y, av.z, av.w};
                float bb[8] = {bv0.x, bv0.y, bv0.z, bv0.w,
                               bv1.x, bv1.y, bv1.z, bv1.w};
#pragma unroll
                for (int i = 0; i < 4; i++)
#pragma unroll
                    for (int j = 0; j < 8; j++)
                        acc[i][j] = fmaf(aa[i], bb[j], acc[i][j]);
            }
            __syncthreads();
        }

        if (p == 0) {
            // s -> g_s
#pragma unroll
            for (int i = 0; i < 4; i++) {
                int gn = node0 + tn * 4 + i;
                if (gn < N) {
                    float4 v0 = make_float4(acc[i][0], acc[i][1], acc[i][2], acc[i][3]);
                    float4 v1 = make_float4(acc[i][4], acc[i][5], acc[i][6], acc[i][7]);
                    *(float4*)&g_s[gn * HDIM + kb]     = v0;
                    *(float4*)&g_s[gn * HDIM + kb + 4] = v1;
                }
            }
        } else {
            // t interleaved with h (from hT) -> g_th: {t2p, t2p+1, h2p, h2p+1}
#pragma unroll
            for (int i = 0; i < 4; i++) {
                int gn = node0 + tn * 4 + i;
                if (gn < N) {
#pragma unroll
                    for (int jp = 0; jp < 4; jp++) {
                        int k = kb + 2 * jp;
                        float h0 = hT[k * 132 + tn * 4 + i];
                        float h1 = hT[(k + 1) * 132 + tn * 4 + i];
                        float4 v = make_float4(acc[i][2 * jp], acc[i][2 * jp + 1], h0, h1);
                        *(float4*)&g_th[(size_t)gn * 128 + (size_t)(k >> 1) * 4] = v;
                    }
                }
            }
        }
    }
}

// ---------------------------------------------------------------------------
// Edge kernel: one warp per edge (grid-strided). Lane owns k = {2*lane, 2*lane+1}.
// W3 (att_w[:,128:144]) lives in registers (32 floats/lane, loaded once).
// Index dtype detected inline per warp (ballot on high words). Indices clamped.
// di-side gather is one LDG.128 (interleaved t/h); scatter is one vector
// atomicAdd(float2) per lane.
// ---------------------------------------------------------------------------
__global__ __launch_bounds__(256) void edge_kernel(
    const void* __restrict__ ei_raw,
    const float* __restrict__ ea,
    const float* __restrict__ att_w,
    float* __restrict__ out,
    int E, int N)
{
    const int lane  = threadIdx.x & 31;
    const int warp  = blockIdx.x * (blockDim.x >> 5) + (threadIdx.x >> 5);
    const int nwarps = gridDim.x * (blockDim.x >> 5);
    const int k0 = lane * 2;
    const int AW = 2 * HDIM + EDIM;  // 144

    // Inline int64-vs-int32 detection: sample 32 odd 32-bit words. All-zero
    // high halves => int64 (indices < 50000). For int32 these words are
    // random indices; P(all 32 == 0) ~ (1/50000)^32.
    const unsigned int* w = (const unsigned int*)ei_raw;
    unsigned int hi = w[2 * lane + 1];
    const int is64 = (__ballot_sync(0xFFFFFFFFu, hi == 0u) == 0xFFFFFFFFu);

    const long long* ei64 = (const long long*)ei_raw;
    const int*       ei32 = (const int*)ei_raw;

    float w3a[16], w3b[16];
#pragma unroll
    for (int q = 0; q < 4; q++) {
        float4 va = *(const float4*)&att_w[k0 * AW + 2 * HDIM + q * 4];
        float4 vb = *(const float4*)&att_w[(k0 + 1) * AW + 2 * HDIM + q * 4];
        w3a[q * 4 + 0] = va.x; w3a[q * 4 + 1] = va.y;
        w3a[q * 4 + 2] = va.z; w3a[q * 4 + 3] = va.w;
        w3b[q * 4 + 0] = vb.x; w3b[q * 4 + 1] = vb.y;
        w3b[q * 4 + 2] = vb.z; w3b[q * 4 + 3] = vb.w;
    }

    const float2* S2  = (const float2*)g_s;
    const float4* TH4 = (const float4*)g_th;
    const float4* EA4 = (const float4*)ea;

#pragma unroll 2
    for (int e = warp; e < E; e += nwarps) {
        int si, di;
        if (is64) {
            si = (int)ei64[e];
            di = (int)ei64[E + e];
        } else {
            si = ei32[e];
            di = ei32[E + e];
        }
        si = min(max(si, 0), N - 1);
        di = min(max(di, 0), N - 1);

        float2 sv  = S2[si * 32 + lane];
        float4 thv = TH4[di * 32 + lane];   // {t0, t1, h0, h1}

        float eav[16];
#pragma unroll
        for (int q = 0; q < 4; q++) {
            float4 v = EA4[e * 4 + q];
            eav[q * 4 + 0] = v.x; eav[q * 4 + 1] = v.y;
            eav[q * 4 + 2] = v.z; eav[q * 4 + 3] = v.w;
        }

        float ax = sv.x + thv.x;
        float ay = sv.y + thv.y;
#pragma unroll
        for (int d = 0; d < 16; d++) {
            ax = fmaf(eav[d], w3a[d], ax);
            ay = fmaf(eav[d], w3b[d], ay);
        }
        ax = (ax > 0.0f) ? ax : 0.2f * ax;
        ay = (ay > 0.0f) ? ay : 0.2f * ay;

        float2 msg = make_float2(thv.z * ax, thv.w * ay);
        atomicAdd((float2*)(out + (size_t)si * HDIM + k0), msg);
    }
}

extern "C" void kernel_launch(void* const* d_in, const int* in_sizes, int n_in,
                              void* d_out, int out_size)
{
    // Resolve inputs by unique element count (robust to metadata ordering).
    const float* x = 0; const void* ei = 0; const float* ea = 0;
    const float* fc_w = 0; const float* fc_b = 0;
    const float* att_w = 0; const float* att_b = 0;

    int big[3] = {-1, -1, -1};
    for (int i = 0; i < n_in; i++) {
        long long s = in_sizes[i];
        if (s == 64 * 128)      { if (!fc_w) fc_w = (const float*)d_in[i]; }
        else if (s == 64 * 144) { if (!att_w) att_w = (const float*)d_in[i]; }
        else if (s == 64) {
            if (!fc_b) fc_b = (const float*)d_in[i];
            else if (!att_b) att_b = (const float*)d_in[i];
        } else {
            if (big[0] < 0) big[0] = i;
            else if (big[1] < 0) big[1] = i;
            else big[2] = i;
        }
    }
    for (int a = 0; a < 3; a++)
        for (int b = a + 1; b < 3; b++)
            if (in_sizes[big[b]] > in_sizes[big[a]]) { int tmp = big[a]; big[a] = big[b]; big[b] = tmp; }
    ea = (const float*)d_in[big[0]];
    x  = (const float*)d_in[big[1]];
    ei = d_in[big[2]];

    const int N = in_sizes[big[1]] / CDIM;   // 50000
    const int E = in_sizes[big[2]] / 2;      // 800000
    float* out = (float*)d_out;

    int tiles = (N + 127) / 128;
    node_kernel<<<tiles, 256>>>(x, fc_w, fc_b, att_w, att_b, out, N);
    edge_kernel<<<1184, 256>>>(ei, ea, att_w, out, E, N);
}

// round 7
// speedup vs baseline: 1.0715x; 1.0715x over previous
#include <cuda_runtime.h>

#define CDIM 128
#define HDIM 64
#define EDIM 16
#define N_MAX 50000
#define E_MAX 1000000

// Scratch:
// g_s [n*64 + k]      = (h @ W1^T)[n][k] + att_b[k]
// g_th[n*128 + k*2+:] = {t_k, h_k} pairs: t = (h @ W2^T)[n][k], h = fc(x)[n][k]
// g_eidx[e]           = {src, dst} as int32, clamped to [0, N)
__device__ float g_s [N_MAX * HDIM];
__device__ float g_th[N_MAX * HDIM * 2];
__device__ int2  g_eidx[E_MAX];

// ---------------------------------------------------------------------------
// Index compaction: int64/int32 auto-detect (per-warp ballot over the first
// 32 odd 32-bit words: all-zero high halves => int64), then grid-stride
// convert+clamp into int2. Removes dtype branch / clamp / 64-bit loads from
// the edge hot loop.
// ---------------------------------------------------------------------------
__global__ __launch_bounds__(256) void compact_kernel(
    const void* __restrict__ ei_raw, int E, int N)
{
    const unsigned int* w = (const unsigned int*)ei_raw;
    unsigned int hi = w[2 * (threadIdx.x & 31) + 1];
    const int is64 = (__ballot_sync(0xFFFFFFFFu, hi == 0u) == 0xFFFFFFFFu);

    const long long* ei64 = (const long long*)ei_raw;
    const int*       ei32 = (const int*)ei_raw;

    int i = blockIdx.x * blockDim.x + threadIdx.x;
    int stride = gridDim.x * blockDim.x;
    for (; i < E; i += stride) {
        int si, di;
        if (is64) { si = (int)ei64[i]; di = (int)ei64[E + i]; }
        else      { si = ei32[i];      di = ei32[E + i]; }
        si = min(max(si, 0), N - 1);
        di = min(max(di, 0), N - 1);
        g_eidx[i] = make_int2(si, di);
    }
}

// ---------------------------------------------------------------------------
// Node kernel: tile of 128 nodes per block, 256 threads.
// Thread tile: 4 nodes x 8 k-outputs (32 accumulators).
// Stage 1: h = x @ fc_w^T + fc_b  (K=128) -> kept in smem hT
// Stage 2: s = h @ W1^T + att_b ; t = h @ W2^T  (K=64)
// Writes g_s and {t,h}-paired g_th; zeroes `out`.
// ---------------------------------------------------------------------------
__global__ __launch_bounds__(256) void node_kernel(
    const float* __restrict__ x,
    const float* __restrict__ fc_w,
    const float* __restrict__ fc_b,
    const float* __restrict__ att_w,
    const float* __restrict__ att_b,
    float* __restrict__ out,
    int N)
{
    __shared__ float hT[64 * 132];
    __shared__ float a_sm[16 * 132];
    __shared__ float b_sm[16 * 68];

    const int t     = threadIdx.x;
    const int tn    = t & 31;
    const int tk    = t >> 5;
    const int kb    = tk * 8;
    const int node0 = blockIdx.x * 128;

    float acc[4][8];

    // ---------------- Stage 1: h ----------------
    {
        float bias[8];
#pragma unroll
        for (int j = 0; j < 8; j++) bias[j] = __ldg(&fc_b[kb + j]);
#pragma unroll
        for (int i = 0; i < 4; i++)
#pragma unroll
            for (int j = 0; j < 8; j++) acc[i][j] = bias[j];

        for (int cb = 0; cb < 8; cb++) {
#pragma unroll
            for (int j = 0; j < 8; j++) {
                int idx = t + j * 256;
                int n = idx >> 4, c = idx & 15;
                int gn = node0 + n;
                float v = (gn < N) ? x[gn * CDIM + cb * 16 + c] : 0.0f;
                a_sm[c * 132 + n] = v;
            }
#pragma unroll
            for (int j = 0; j < 4; j++) {
                int idx = t + j * 256;
                int k = idx >> 4, c = idx & 15;
                b_sm[c * 68 + k] = fc_w[k * CDIM + cb * 16 + c];
            }
            __syncthreads();
#pragma unroll
            for (int c = 0; c < 16; c++) {
                float4 av  = *(const float4*)&a_sm[c * 132 + tn * 4];
                float4 bv0 = *(const float4*)&b_sm[c * 68 + kb];
                float4 bv1 = *(const float4*)&b_sm[c * 68 + kb + 4];
                float aa[4] = {av.x, av.y, av.z, av.w};
                float bb[8] = {bv0.x, bv0.y, bv0.z, bv0.w,
                               bv1.x, bv1.y, bv1.z, bv1.w};
#pragma unroll
                for (int i = 0; i < 4; i++)
#pragma unroll
                    for (int j = 0; j < 8; j++)
                        acc[i][j] = fmaf(aa[i], bb[j], acc[i][j]);
            }
            __syncthreads();
        }

#pragma unroll
        for (int i = 0; i < 4; i++) {
            int gn = node0 + tn * 4 + i;
            if (gn < N) {
                float4 z = make_float4(0.f, 0.f, 0.f, 0.f);
                *(float4*)&out[(size_t)gn * HDIM + kb]     = z;
                *(float4*)&out[(size_t)gn * HDIM + kb + 4] = z;
            }
#pragma unroll
            for (int j = 0; j < 8; j++)
                hT[(kb + j) * 132 + tn * 4 + i] = acc[i][j];
        }
        __syncthreads();
    }

    // ---------------- Stage 2: s (p=0) and t (p=1) ----------------
    for (int p = 0; p < 2; p++) {
        float bias[8];
#pragma unroll
        for (int j = 0; j < 8; j++)
            bias[j] = (p == 0) ? __ldg(&att_b[kb + j]) : 0.0f;
#pragma unroll
        for (int i = 0; i < 4; i++)
#pragma unroll
            for (int j = 0; j < 8; j++) acc[i][j] = bias[j];

        for (int cb = 0; cb < 4; cb++) {
#pragma unroll
            for (int j = 0; j < 4; j++) {
                int idx = t + j * 256;
                int k = idx >> 4, c = idx & 15;
                b_sm[c * 68 + k] = att_w[k * (2 * HDIM + EDIM) + p * 64 + cb * 16 + c];
            }
            __syncthreads();
#pragma unroll
            for (int c16 = 0; c16 < 16; c16++) {
                int c = cb * 16 + c16;
                float4 av  = *(const float4*)&hT[c * 132 + tn * 4];
                float4 bv0 = *(const float4*)&b_sm[c16 * 68 + kb];
                float4 bv1 = *(const float4*)&b_sm[c16 * 68 + kb + 4];
                float aa[4] = {av.x, av.y, av.z, av.w};
                float bb[8] = {bv0.x, bv0.y, bv0.z, bv0.w,
                               bv1.x, bv1.y, bv1.z, bv1.w};
#pragma unroll
                for (int i = 0; i < 4; i++)
#pragma unroll
                    for (int j = 0; j < 8; j++)
                        acc[i][j] = fmaf(aa[i], bb[j], acc[i][j]);
            }
            __syncthreads();
        }

        if (p == 0) {
#pragma unroll
            for (int i = 0; i < 4; i++) {
                int gn = node0 + tn * 4 + i;
                if (gn < N) {
                    float4 v0 = make_float4(acc[i][0], acc[i][1], acc[i][2], acc[i][3]);
                    float4 v1 = make_float4(acc[i][4], acc[i][5], acc[i][6], acc[i][7]);
                    *(float4*)&g_s[gn * HDIM + kb]     = v0;
                    *(float4*)&g_s[gn * HDIM + kb + 4] = v1;
                }
            }
        } else {
            // {t_k, h_k} pairs: float4 {t_k, h_k, t_{k+1}, h_{k+1}} at [gn*128 + k*2]
#pragma unroll
            for (int i = 0; i < 4; i++) {
                int gn = node0 + tn * 4 + i;
                if (gn < N) {
#pragma unroll
                    for (int jp = 0; jp < 4; jp++) {
                        int k = kb + 2 * jp;
                        float h0 = hT[k * 132 + tn * 4 + i];
                        float h1 = hT[(k + 1) * 132 + tn * 4 + i];
                        float4 v = make_float4(acc[i][2 * jp], h0, acc[i][2 * jp + 1], h1);
                        *(float4*)&g_th[(size_t)gn * 128 + (size_t)k * 2] = v;
                    }
                }
            }
        }
    }
}

// ---------------------------------------------------------------------------
// Edge kernel v2: 64-thread group per edge (2 warps, no intra-group sync
// needed), lane owns k = lane64. W3 row in 16 registers. Software pipeline:
// indices 2 iterations ahead, s/{t,h} gathers 1 iteration ahead. edge_attr:
// 4 independent broadcast LDG.128 per iteration. Scalar RED scatter.
// ---------------------------------------------------------------------------
__global__ __launch_bounds__(256, 4) void edge_kernel(
    const float* __restrict__ ea,
    const float* __restrict__ att_w,
    float* __restrict__ out,
    int E)
{
    const int lane64 = threadIdx.x & 63;
    const int grp    = blockIdx.x * (blockDim.x >> 6) + (threadIdx.x >> 6);
    const int ngrp   = gridDim.x * (blockDim.x >> 6);
    const int AW     = 2 * HDIM + EDIM;  // 144

    // W3 row for this lane's k: att_w[k][128..143]
    float w3[16];
#pragma unroll
    for (int q = 0; q < 4; q++) {
        float4 v = *(const float4*)&att_w[lane64 * AW + 2 * HDIM + q * 4];
        w3[q * 4 + 0] = v.x; w3[q * 4 + 1] = v.y;
        w3[q * 4 + 2] = v.z; w3[q * 4 + 3] = v.w;
    }

    const float*  S   = g_s;
    const float2* TH2 = (const float2*)g_th;
    const float4* EA4 = (const float4*)ea;

    // Pipeline prologue: e0 = current, e1 = next.
    int e0 = grp;
    if (e0 >= E) return;
    int e1 = e0 + ngrp;

    int2 p0 = g_eidx[e0];
    int2 p1 = (e1 < E) ? g_eidx[e1] : p0;

    float  sv0 = S[p0.x * HDIM + lane64];
    float2 th0 = TH2[p0.y * HDIM + lane64];

    while (true) {
        // Prefetch gathers for e1 and indices for e2 (issued early, consumed
        // next iteration -> latency hidden behind this iteration's work).
        float  sv1 = 0.0f;
        float2 th1 = make_float2(0.0f, 0.0f);
        if (e1 < E) {
            sv1 = S[p1.x * HDIM + lane64];
            th1 = TH2[p1.y * HDIM + lane64];
        }
        int e2 = e1 + ngrp;
        int2 p2 = (e2 < E) ? g_eidx[e2] : p1;

        // edge_attr for current edge: 4 independent broadcast LDG.128.
        float4 a0 = EA4[e0 * 4 + 0];
        float4 a1 = EA4[e0 * 4 + 1];
        float4 a2 = EA4[e0 * 4 + 2];
        float4 a3 = EA4[e0 * 4 + 3];

        float acc = sv0 + th0.x;   // s_i[k] + t_j[k]
        acc = fmaf(a0.x, w3[0],  acc); acc = fmaf(a0.y, w3[1],  acc);
        acc = fmaf(a0.z, w3[2],  acc); acc = fmaf(a0.w, w3[3],  acc);
        acc = fmaf(a1.x, w3[4],  acc); acc = fmaf(a1.y, w3[5],  acc);
        acc = fmaf(a1.z, w3[6],  acc); acc = fmaf(a1.w, w3[7],  acc);
        acc = fmaf(a2.x, w3[8],  acc); acc = fmaf(a2.y, w3[9],  acc);
        acc = fmaf(a2.z, w3[10], acc); acc = fmaf(a2.w, w3[11], acc);
        acc = fmaf(a3.x, w3[12], acc); acc = fmaf(a3.y, w3[13], acc);
        acc = fmaf(a3.z, w3[14], acc); acc = fmaf(a3.w, w3[15], acc);

        acc = (acc > 0.0f) ? acc : 0.2f * acc;        // leaky_relu(0.2)
        atomicAdd(out + (size_t)p0.x * HDIM + lane64, th0.y * acc);  // h_j[k]*alpha

        // Rotate pipeline.
        e0 = e1; p0 = p1; sv0 = sv1; th0 = th1;
        e1 = e2; p1 = p2;
        if (e0 >= E) break;
    }
}

extern "C" void kernel_launch(void* const* d_in, const int* in_sizes, int n_in,
                              void* d_out, int out_size)
{
    // Resolve inputs by unique element count (robust to metadata ordering).
    const float* x = 0; const void* ei = 0; const float* ea = 0;
    const float* fc_w = 0; const float* fc_b = 0;
    const float* att_w = 0; const float* att_b = 0;

    int big[3] = {-1, -1, -1};
    for (int i = 0; i < n_in; i++) {
        long long s = in_sizes[i];
        if (s == 64 * 128)      { if (!fc_w) fc_w = (const float*)d_in[i]; }
        else if (s == 64 * 144) { if (!att_w) att_w = (const float*)d_in[i]; }
        else if (s == 64) {
            if (!fc_b) fc_b = (const float*)d_in[i];
            else if (!att_b) att_b = (const float*)d_in[i];
        } else {
            if (big[0] < 0) big[0] = i;
            else if (big[1] < 0) big[1] = i;
            else big[2] = i;
        }
    }
    for (int a = 0; a < 3; a++)
        for (int b = a + 1; b < 3; b++)
            if (in_sizes[big[b]] > in_sizes[big[a]]) { int tmp = big[a]; big[a] = big[b]; big[b] = tmp; }
    ea = (const float*)d_in[big[0]];
    x  = (const float*)d_in[big[1]];
    ei = d_in[big[2]];

    const int N = in_sizes[big[1]] / CDIM;   // 50000
    const int E = in_sizes[big[2]] / 2;      // 800000
    float* out = (float*)d_out;

    compact_kernel<<<512, 256>>>(ei, E, N);
    int tiles = (N + 127) / 128;
    node_kernel<<<tiles, 256>>>(x, fc_w, fc_b, att_w, att_b, out, N);
    edge_kernel<<<1184, 256>>>(ea, att_w, out, E);
}

// round 8
// speedup vs baseline: 1.4109x; 1.3167x over previous
#include <cuda_runtime.h>

#define CDIM 128
#define HDIM 64
#define EDIM 16
#define N_MAX 50000
#define E_MAX 810000

// Node-level precompute (float4 layout, 16 float4 per node row):
//  g_s4[n*16+q] = (h@W1^T + att_b)[n][4q..4q+3]
//  g_t4[n*16+q] = (h@W2^T)[n][4q..4q+3]
//  g_h4[n*16+q] = (x@fc_w^T + fc_b)[n][4q..4q+3]
// Edge-level precompute:
//  g_r4[e*16+q] = (edge_attr@W3^T)[e][4q..4q+3]
//  g_eidx[e]    = {src, dst} int32, clamped to [0,N)
__device__ float4 g_s4[N_MAX * 16];
__device__ float4 g_t4[N_MAX * 16];
__device__ float4 g_h4[N_MAX * 16];
__device__ float4 g_r4[(size_t)E_MAX * 16];
__device__ int2   g_eidx[E_MAX];

// ---------------------------------------------------------------------------
// Index compaction: int64/int32 auto-detect (ballot over first 32 odd words;
// all-zero high halves => int64), convert + clamp into int2.
// ---------------------------------------------------------------------------
__global__ __launch_bounds__(256) void compact_kernel(
    const void* __restrict__ ei_raw, int E, int N)
{
    const unsigned int* w = (const unsigned int*)ei_raw;
    unsigned int hi = w[2 * (threadIdx.x & 31) + 1];
    const int is64 = (__ballot_sync(0xFFFFFFFFu, hi == 0u) == 0xFFFFFFFFu);

    const long long* ei64 = (const long long*)ei_raw;
    const int*       ei32 = (const int*)ei_raw;

    int i = blockIdx.x * blockDim.x + threadIdx.x;
    int stride = gridDim.x * blockDim.x;
    for (; i < E; i += stride) {
        int si, di;
        if (is64) { si = (int)ei64[i]; di = (int)ei64[E + i]; }
        else      { si = ei32[i];      di = ei32[E + i]; }
        si = min(max(si, 0), N - 1);
        di = min(max(di, 0), N - 1);
        g_eidx[i] = make_int2(si, di);
    }
}

// ---------------------------------------------------------------------------
// r-GEMM: r[e][k] = sum_d ea[e][d] * W3[k][d]   (W3 = att_w[:,128:144])
// Warp per edge (grid-strided), lane owns k-pair {2l, 2l+1}; W3 in 32 regs.
// Streaming, coalesced, no gathers, no atomics.
// ---------------------------------------------------------------------------
__global__ __launch_bounds__(256) void rw_kernel(
    const float* __restrict__ ea,
    const float* __restrict__ att_w,
    int E)
{
    const int lane   = threadIdx.x & 31;
    const int warp   = blockIdx.x * (blockDim.x >> 5) + (threadIdx.x >> 5);
    const int nwarps = gridDim.x * (blockDim.x >> 5);
    const int AW     = 2 * HDIM + EDIM;  // 144
    const int k0     = lane * 2;

    float w3a[16], w3b[16];
#pragma unroll
    for (int q = 0; q < 4; q++) {
        float4 va = *(const float4*)&att_w[k0 * AW + 2 * HDIM + q * 4];
        float4 vb = *(const float4*)&att_w[(k0 + 1) * AW + 2 * HDIM + q * 4];
        w3a[q * 4 + 0] = va.x; w3a[q * 4 + 1] = va.y;
        w3a[q * 4 + 2] = va.z; w3a[q * 4 + 3] = va.w;
        w3b[q * 4 + 0] = vb.x; w3b[q * 4 + 1] = vb.y;
        w3b[q * 4 + 2] = vb.z; w3b[q * 4 + 3] = vb.w;
    }

    const float4* EA4 = (const float4*)ea;
    float2* R2 = (float2*)g_r4;

    for (int e = warp; e < E; e += nwarps) {
        float4 a0 = EA4[e * 4 + 0];
        float4 a1 = EA4[e * 4 + 1];
        float4 a2 = EA4[e * 4 + 2];
        float4 a3 = EA4[e * 4 + 3];
        float av[16] = {a0.x, a0.y, a0.z, a0.w, a1.x, a1.y, a1.z, a1.w,
                        a2.x, a2.y, a2.z, a2.w, a3.x, a3.y, a3.z, a3.w};
        float rx = 0.0f, ry = 0.0f;
#pragma unroll
        for (int d = 0; d < 16; d++) {
            rx = fmaf(av[d], w3a[d], rx);
            ry = fmaf(av[d], w3b[d], ry);
        }
        R2[(size_t)e * 32 + lane] = make_float2(rx, ry);  // coalesced 256B/warp
    }
}

// ---------------------------------------------------------------------------
// Node kernel: tile of 128 nodes per block, 256 threads, 4x8 thread tile.
// Stage 1: h = x@fc_w^T + fc_b (K=128) -> g_h4 + smem hT; zeroes out.
// Stage 2: s = h@W1^T + att_b -> g_s4 ;  t = h@W2^T -> g_t4.
// ---------------------------------------------------------------------------
__global__ __launch_bounds__(256) void node_kernel(
    const float* __restrict__ x,
    const float* __restrict__ fc_w,
    const float* __restrict__ fc_b,
    const float* __restrict__ att_w,
    const float* __restrict__ att_b,
    float* __restrict__ out,
    int N)
{
    __shared__ float hT[64 * 132];
    __shared__ float a_sm[16 * 132];
    __shared__ float b_sm[16 * 68];

    const int t     = threadIdx.x;
    const int tn    = t & 31;
    const int tk    = t >> 5;
    const int kb    = tk * 8;
    const int node0 = blockIdx.x * 128;

    float acc[4][8];

    // ---------------- Stage 1: h ----------------
    {
        float bias[8];
#pragma unroll
        for (int j = 0; j < 8; j++) bias[j] = __ldg(&fc_b[kb + j]);
#pragma unroll
        for (int i = 0; i < 4; i++)
#pragma unroll
            for (int j = 0; j < 8; j++) acc[i][j] = bias[j];

        for (int cb = 0; cb < 8; cb++) {
#pragma unroll
            for (int j = 0; j < 8; j++) {
                int idx = t + j * 256;
                int n = idx >> 4, c = idx & 15;
                int gn = node0 + n;
                float v = (gn < N) ? x[gn * CDIM + cb * 16 + c] : 0.0f;
                a_sm[c * 132 + n] = v;
            }
#pragma unroll
            for (int j = 0; j < 4; j++) {
                int idx = t + j * 256;
                int k = idx >> 4, c = idx & 15;
                b_sm[c * 68 + k] = fc_w[k * CDIM + cb * 16 + c];
            }
            __syncthreads();
#pragma unroll
            for (int c = 0; c < 16; c++) {
                float4 av  = *(const float4*)&a_sm[c * 132 + tn * 4];
                float4 bv0 = *(const float4*)&b_sm[c * 68 + kb];
                float4 bv1 = *(const float4*)&b_sm[c * 68 + kb + 4];
                float aa[4] = {av.x, av.y, av.z, av.w};
                float bb[8] = {bv0.x, bv0.y, bv0.z, bv0.w,
                               bv1.x, bv1.y, bv1.z, bv1.w};
#pragma unroll
                for (int i = 0; i < 4; i++)
#pragma unroll
                    for (int j = 0; j < 8; j++)
                        acc[i][j] = fmaf(aa[i], bb[j], acc[i][j]);
            }
            __syncthreads();
        }

#pragma unroll
        for (int i = 0; i < 4; i++) {
            int gn = node0 + tn * 4 + i;
            if (gn < N) {
                float4 v0 = make_float4(acc[i][0], acc[i][1], acc[i][2], acc[i][3]);
                float4 v1 = make_float4(acc[i][4], acc[i][5], acc[i][6], acc[i][7]);
                g_h4[gn * 16 + (kb >> 2)]     = v0;
                g_h4[gn * 16 + (kb >> 2) + 1] = v1;
                float4 z = make_float4(0.f, 0.f, 0.f, 0.f);
                *(float4*)&out[(size_t)gn * HDIM + kb]     = z;
                *(float4*)&out[(size_t)gn * HDIM + kb + 4] = z;
            }
#pragma unroll
            for (int j = 0; j < 8; j++)
                hT[(kb + j) * 132 + tn * 4 + i] = acc[i][j];
        }
        __syncthreads();
    }

    // ---------------- Stage 2: s (p=0) and t (p=1) ----------------
    for (int p = 0; p < 2; p++) {
        float bias[8];
#pragma unroll
        for (int j = 0; j < 8; j++)
            bias[j] = (p == 0) ? __ldg(&att_b[kb + j]) : 0.0f;
#pragma unroll
        for (int i = 0; i < 4; i++)
#pragma unroll
            for (int j = 0; j < 8; j++) acc[i][j] = bias[j];

        for (int cb = 0; cb < 4; cb++) {
#pragma unroll
            for (int j = 0; j < 4; j++) {
                int idx = t + j * 256;
                int k = idx >> 4, c = idx & 15;
                b_sm[c * 68 + k] = att_w[k * (2 * HDIM + EDIM) + p * 64 + cb * 16 + c];
            }
            __syncthreads();
#pragma unroll
            for (int c16 = 0; c16 < 16; c16++) {
                int c = cb * 16 + c16;
                float4 av  = *(const float4*)&hT[c * 132 + tn * 4];
                float4 bv0 = *(const float4*)&b_sm[c16 * 68 + kb];
                float4 bv1 = *(const float4*)&b_sm[c16 * 68 + kb + 4];
                float aa[4] = {av.x, av.y, av.z, av.w};
                float bb[8] = {bv0.x, bv0.y, bv0.z, bv0.w,
                               bv1.x, bv1.y, bv1.z, bv1.w};
#pragma unroll
                for (int i = 0; i < 4; i++)
#pragma unroll
                    for (int j = 0; j < 8; j++)
                        acc[i][j] = fmaf(aa[i], bb[j], acc[i][j]);
            }
            __syncthreads();
        }

        float4* dst = (p == 0) ? g_s4 : g_t4;
#pragma unroll
        for (int i = 0; i < 4; i++) {
            int gn = node0 + tn * 4 + i;
            if (gn < N) {
                float4 v0 = make_float4(acc[i][0], acc[i][1], acc[i][2], acc[i][3]);
                float4 v1 = make_float4(acc[i][4], acc[i][5], acc[i][6], acc[i][7]);
                dst[gn * 16 + (kb >> 2)]     = v0;
                dst[gn * 16 + (kb >> 2) + 1] = v1;
            }
        }
    }
}

// ---------------------------------------------------------------------------
// Edge kernel v3: warp processes 2 edges per iteration. Half-warp per edge,
// lane owns k-quad q = (lane&15)*4. No weights in the kernel at all:
// per lane: 4 gather LDG.128 (s, t, h, r) + adds + leaky + mul + 1 vector RED.
// ~40 regs -> high occupancy; 8+ independent LDGs in flight per warp-iter.
// ---------------------------------------------------------------------------
__global__ __launch_bounds__(256) void edge_kernel(
    float* __restrict__ out,
    int E)
{
    const int lane = threadIdx.x & 31;
    const int eh   = lane >> 4;        // which edge of the pair
    const int q    = lane & 15;        // k-quad index
    const int warp = blockIdx.x * (blockDim.x >> 5) + (threadIdx.x >> 5);
    const int nw   = gridDim.x * (blockDim.x >> 5);

    for (int e2 = warp * 2; e2 < E; e2 += nw * 2) {
        int e = e2 + eh;
        if (e >= E) continue;

        int2 p = g_eidx[e];

        float4 s4 = g_s4[p.x * 16 + q];
        float4 t4 = g_t4[p.y * 16 + q];
        float4 h4 = g_h4[p.y * 16 + q];
        float4 r4 = g_r4[(size_t)e * 16 + q];

        float ax = s4.x + t4.x + r4.x;
        float ay = s4.y + t4.y + r4.y;
        float az = s4.z + t4.z + r4.z;
        float aw = s4.w + t4.w + r4.w;
        ax = (ax > 0.0f) ? ax : 0.2f * ax;
        ay = (ay > 0.0f) ? ay : 0.2f * ay;
        az = (az > 0.0f) ? az : 0.2f * az;
        aw = (aw > 0.0f) ? aw : 0.2f * aw;

        float mx = h4.x * ax;
        float my = h4.y * ay;
        float mz = h4.z * az;
        float mw = h4.w * aw;

        float* addr = out + (size_t)p.x * HDIM + q * 4;
        asm volatile("red.global.add.v4.f32 [%0], {%1, %2, %3, %4};"
                     :: "l"(addr), "f"(mx), "f"(my), "f"(mz), "f"(mw)
                     : "memory");
    }
}

extern "C" void kernel_launch(void* const* d_in, const int* in_sizes, int n_in,
                              void* d_out, int out_size)
{
    // Resolve inputs by unique element count (robust to metadata ordering).
    const float* x = 0; const void* ei = 0; const float* ea = 0;
    const float* fc_w = 0; const float* fc_b = 0;
    const float* att_w = 0; const float* att_b = 0;

    int big[3] = {-1, -1, -1};
    for (int i = 0; i < n_in; i++) {
        long long s = in_sizes[i];
        if (s == 64 * 128)      { if (!fc_w) fc_w = (const float*)d_in[i]; }
        else if (s == 64 * 144) { if (!att_w) att_w = (const float*)d_in[i]; }
        else if (s == 64) {
            if (!fc_b) fc_b = (const float*)d_in[i];
            else if (!att_b) att_b = (const float*)d_in[i];
        } else {
            if (big[0] < 0) big[0] = i;
            else if (big[1] < 0) big[1] = i;
            else big[2] = i;
        }
    }
    for (int a = 0; a < 3; a++)
        for (int b = a + 1; b < 3; b++)
            if (in_sizes[big[b]] > in_sizes[big[a]]) { int tmp = big[a]; big[a] = big[b]; big[b] = tmp; }
    ea = (const float*)d_in[big[0]];
    x  = (const float*)d_in[big[1]];
    ei = d_in[big[2]];

    const int N = in_sizes[big[1]] / CDIM;   // 50000
    int E = in_sizes[big[2]] / 2;            // 800000
    if (E > E_MAX) E = E_MAX;
    float* out = (float*)d_out;

    compact_kernel<<<512, 256>>>(ei, E, N);
    rw_kernel<<<1184, 256>>>(ea, att_w, E);
    int tiles = (N + 127) / 128;
    node_kernel<<<tiles, 256>>>(x, fc_w, fc_b, att_w, att_b, out, N);
    edge_kernel<<<1184, 256>>>(out, E);
}

// round 9
// speedup vs baseline: 1.5519x; 1.1000x over previous
#include <cuda_runtime.h>
#include <cuda_fp16.h>

#define CDIM 128
#define HDIM 64
#define EDIM 16
#define N_MAX 50000
#define E_MAX 810000

// Node-level precompute (float4 layout, 16 float4 per node row):
//  g_s4[n*16+q] = (h@W1^T + att_b)[n][4q..4q+3]
//  g_t4[n*16+q] = (h@W2^T)[n][4q..4q+3]
//  g_h4[n*16+q] = (x@fc_w^T + fc_b)[n][4q..4q+3]
// Edge-level precompute:
//  g_r2[e*32+p] = half2{r[2p], r[2p+1]},  r = edge_attr@W3^T  (fp16 storage:
//                 r ~ N(0,0.33^2) inside alpha of sigma~1 -> ~1.6e-4 rel err)
//  g_eidx[e]    = {src, dst} int32, clamped to [0,N)
__device__ float4  g_s4[N_MAX * 16];
__device__ float4  g_t4[N_MAX * 16];
__device__ float4  g_h4[N_MAX * 16];
__device__ __half2 g_r2[(size_t)E_MAX * 32];
__device__ int2    g_eidx[E_MAX];

// ---------------------------------------------------------------------------
// Prep kernel (fused): phase A converts edge_index (int64/int32 auto-detected
// via ballot on high words) into clamped int2; phase B computes the r-GEMM
// r[e][k] = ea[e] . W3[k] (warp per edge, W3 in 32 regs) and stores fp16.
// Phases are independent grid-stride loops; only edge_kernel (a later launch)
// consumes their outputs, so no intra-kernel ordering is needed.
// ---------------------------------------------------------------------------
__global__ __launch_bounds__(256) void prep_kernel(
    const void* __restrict__ ei_raw,
    const float* __restrict__ ea,
    const float* __restrict__ att_w,
    int E, int N)
{
    const int lane = threadIdx.x & 31;

    // ---- phase A: index compaction ----
    {
        const unsigned int* w = (const unsigned int*)ei_raw;
        unsigned int hi = w[2 * lane + 1];
        const int is64 = (__ballot_sync(0xFFFFFFFFu, hi == 0u) == 0xFFFFFFFFu);

        const long long* ei64 = (const long long*)ei_raw;
        const int*       ei32 = (const int*)ei_raw;

        int i = blockIdx.x * blockDim.x + threadIdx.x;
        int stride = gridDim.x * blockDim.x;
        for (; i < E; i += stride) {
            int si, di;
            if (is64) { si = (int)ei64[i]; di = (int)ei64[E + i]; }
            else      { si = ei32[i];      di = ei32[E + i]; }
            si = min(max(si, 0), N - 1);
            di = min(max(di, 0), N - 1);
            g_eidx[i] = make_int2(si, di);
        }
    }

    // ---- phase B: r-GEMM, warp per edge, lane owns k-pair {2l, 2l+1} ----
    const int warp   = blockIdx.x * (blockDim.x >> 5) + (threadIdx.x >> 5);
    const int nwarps = gridDim.x * (blockDim.x >> 5);
    const int AW     = 2 * HDIM + EDIM;  // 144
    const int k0     = lane * 2;

    float w3a[16], w3b[16];
#pragma unroll
    for (int q = 0; q < 4; q++) {
        float4 va = *(const float4*)&att_w[k0 * AW + 2 * HDIM + q * 4];
        float4 vb = *(const float4*)&att_w[(k0 + 1) * AW + 2 * HDIM + q * 4];
        w3a[q * 4 + 0] = va.x; w3a[q * 4 + 1] = va.y;
        w3a[q * 4 + 2] = va.z; w3a[q * 4 + 3] = va.w;
        w3b[q * 4 + 0] = vb.x; w3b[q * 4 + 1] = vb.y;
        w3b[q * 4 + 2] = vb.z; w3b[q * 4 + 3] = vb.w;
    }

    const float4* EA4 = (const float4*)ea;
    for (int e = warp; e < E; e += nwarps) {
        float4 a0 = EA4[e * 4 + 0];
        float4 a1 = EA4[e * 4 + 1];
        float4 a2 = EA4[e * 4 + 2];
        float4 a3 = EA4[e * 4 + 3];
        float av[16] = {a0.x, a0.y, a0.z, a0.w, a1.x, a1.y, a1.z, a1.w,
                        a2.x, a2.y, a2.z, a2.w, a3.x, a3.y, a3.z, a3.w};
        float rx = 0.0f, ry = 0.0f;
#pragma unroll
        for (int d = 0; d < 16; d++) {
            rx = fmaf(av[d], w3a[d], rx);
            ry = fmaf(av[d], w3b[d], ry);
        }
        g_r2[(size_t)e * 32 + lane] = __floats2half2_rn(rx, ry);  // 128B/warp
    }
}

// ---------------------------------------------------------------------------
// Node kernel: tile of 128 nodes per block, 256 threads, 4x8 thread tile.
// Stage 1: h = x@fc_w^T + fc_b (K=128) -> g_h4 + smem hT; zeroes out.
// Stage 2: s = h@W1^T + att_b -> g_s4 ;  t = h@W2^T -> g_t4.
// ---------------------------------------------------------------------------
__global__ __launch_bounds__(256) void node_kernel(
    const float* __restrict__ x,
    const float* __restrict__ fc_w,
    const float* __restrict__ fc_b,
    const float* __restrict__ att_w,
    const float* __restrict__ att_b,
    float* __restrict__ out,
    int N)
{
    __shared__ float hT[64 * 132];
    __shared__ float a_sm[16 * 132];
    __shared__ float b_sm[16 * 68];

    const int t     = threadIdx.x;
    const int tn    = t & 31;
    const int tk    = t >> 5;
    const int kb    = tk * 8;
    const int node0 = blockIdx.x * 128;

    float acc[4][8];

    // ---------------- Stage 1: h ----------------
    {
        float bias[8];
#pragma unroll
        for (int j = 0; j < 8; j++) bias[j] = __ldg(&fc_b[kb + j]);
#pragma unroll
        for (int i = 0; i < 4; i++)
#pragma unroll
            for (int j = 0; j < 8; j++) acc[i][j] = bias[j];

        for (int cb = 0; cb < 8; cb++) {
#pragma unroll
            for (int j = 0; j < 8; j++) {
                int idx = t + j * 256;
                int n = idx >> 4, c = idx & 15;
                int gn = node0 + n;
                float v = (gn < N) ? x[gn * CDIM + cb * 16 + c] : 0.0f;
                a_sm[c * 132 + n] = v;
            }
#pragma unroll
            for (int j = 0; j < 4; j++) {
                int idx = t + j * 256;
                int k = idx >> 4, c = idx & 15;
                b_sm[c * 68 + k] = fc_w[k * CDIM + cb * 16 + c];
            }
            __syncthreads();
#pragma unroll
            for (int c = 0; c < 16; c++) {
                float4 av  = *(const float4*)&a_sm[c * 132 + tn * 4];
                float4 bv0 = *(const float4*)&b_sm[c * 68 + kb];
                float4 bv1 = *(const float4*)&b_sm[c * 68 + kb + 4];
                float aa[4] = {av.x, av.y, av.z, av.w};
                float bb[8] = {bv0.x, bv0.y, bv0.z, bv0.w,
                               bv1.x, bv1.y, bv1.z, bv1.w};
#pragma unroll
                for (int i = 0; i < 4; i++)
#pragma unroll
                    for (int j = 0; j < 8; j++)
                        acc[i][j] = fmaf(aa[i], bb[j], acc[i][j]);
            }
            __syncthreads();
        }

#pragma unroll
        for (int i = 0; i < 4; i++) {
            int gn = node0 + tn * 4 + i;
            if (gn < N) {
                float4 v0 = make_float4(acc[i][0], acc[i][1], acc[i][2], acc[i][3]);
                float4 v1 = make_float4(acc[i][4], acc[i][5], acc[i][6], acc[i][7]);
                g_h4[gn * 16 + (kb >> 2)]     = v0;
                g_h4[gn * 16 + (kb >> 2) + 1] = v1;
                float4 z = make_float4(0.f, 0.f, 0.f, 0.f);
                *(float4*)&out[(size_t)gn * HDIM + kb]     = z;
                *(float4*)&out[(size_t)gn * HDIM + kb + 4] = z;
            }
#pragma unroll
            for (int j = 0; j < 8; j++)
                hT[(kb + j) * 132 + tn * 4 + i] = acc[i][j];
        }
        __syncthreads();
    }

    // ---------------- Stage 2: s (p=0) and t (p=1) ----------------
    for (int p = 0; p < 2; p++) {
        float bias[8];
#pragma unroll
        for (int j = 0; j < 8; j++)
            bias[j] = (p == 0) ? __ldg(&att_b[kb + j]) : 0.0f;
#pragma unroll
        for (int i = 0; i < 4; i++)
#pragma unroll
            for (int j = 0; j < 8; j++) acc[i][j] = bias[j];

        for (int cb = 0; cb < 4; cb++) {
#pragma unroll
            for (int j = 0; j < 4; j++) {
                int idx = t + j * 256;
                int k = idx >> 4, c = idx & 15;
                b_sm[c * 68 + k] = att_w[k * (2 * HDIM + EDIM) + p * 64 + cb * 16 + c];
            }
            __syncthreads();
#pragma unroll
            for (int c16 = 0; c16 < 16; c16++) {
                int c = cb * 16 + c16;
                float4 av  = *(const float4*)&hT[c * 132 + tn * 4];
                float4 bv0 = *(const float4*)&b_sm[c16 * 68 + kb];
                float4 bv1 = *(const float4*)&b_sm[c16 * 68 + kb + 4];
                float aa[4] = {av.x, av.y, av.z, av.w};
                float bb[8] = {bv0.x, bv0.y, bv0.z, bv0.w,
                               bv1.x, bv1.y, bv1.z, bv1.w};
#pragma unroll
                for (int i = 0; i < 4; i++)
#pragma unroll
                    for (int j = 0; j < 8; j++)
                        acc[i][j] = fmaf(aa[i], bb[j], acc[i][j]);
            }
            __syncthreads();
        }

        float4* dst = (p == 0) ? g_s4 : g_t4;
#pragma unroll
        for (int i = 0; i < 4; i++) {
            int gn = node0 + tn * 4 + i;
            if (gn < N) {
                float4 v0 = make_float4(acc[i][0], acc[i][1], acc[i][2], acc[i][3]);
                float4 v1 = make_float4(acc[i][4], acc[i][5], acc[i][6], acc[i][7]);
                dst[gn * 16 + (kb >> 2)]     = v0;
                dst[gn * 16 + (kb >> 2) + 1] = v1;
            }
        }
    }
}

// ---------------------------------------------------------------------------
// Edge kernel v3.1: warp processes 2 edges; half-warp per edge, lane owns
// k-quad q. Per lane: 3 gather LDG.128 (s,t,h) + 1 LDG.64 (fp16 r) + adds +
// leaky + mul + 1 vector RED. ~30 regs -> ~full occupancy.
// ---------------------------------------------------------------------------
__global__ __launch_bounds__(256) void edge_kernel(
    float* __restrict__ out,
    int E)
{
    const int lane = threadIdx.x & 31;
    const int eh   = lane >> 4;        // which edge of the pair
    const int q    = lane & 15;        // k-quad index
    const int warp = blockIdx.x * (blockDim.x >> 5) + (threadIdx.x >> 5);
    const int nw   = gridDim.x * (blockDim.x >> 5);

    const uint2* R64 = (const uint2*)g_r2;   // one uint2 = 2 half2 = 4 halves

    for (int e2 = warp * 2; e2 < E; e2 += nw * 2) {
        int e = e2 + eh;
        if (e >= E) continue;

        int2 p = g_eidx[e];

        float4 s4 = g_s4[p.x * 16 + q];
        float4 t4 = g_t4[p.y * 16 + q];
        float4 h4 = g_h4[p.y * 16 + q];
        uint2 rr  = R64[(size_t)e * 16 + q];
        float2 r01 = __half22float2(*reinterpret_cast<const __half2*>(&rr.x));
        float2 r23 = __half22float2(*reinterpret_cast<const __half2*>(&rr.y));

        float ax = s4.x + t4.x + r01.x;
        float ay = s4.y + t4.y + r01.y;
        float az = s4.z + t4.z + r23.x;
        float aw = s4.w + t4.w + r23.y;
        ax = (ax > 0.0f) ? ax : 0.2f * ax;
        ay = (ay > 0.0f) ? ay : 0.2f * ay;
        az = (az > 0.0f) ? az : 0.2f * az;
        aw = (aw > 0.0f) ? aw : 0.2f * aw;

        float mx = h4.x * ax;
        float my = h4.y * ay;
        float mz = h4.z * az;
        float mw = h4.w * aw;

        float* addr = out + (size_t)p.x * HDIM + q * 4;
        asm volatile("red.global.add.v4.f32 [%0], {%1, %2, %3, %4};"
                     :: "l"(addr), "f"(mx), "f"(my), "f"(mz), "f"(mw)
                     : "memory");
    }
}

extern "C" void kernel_launch(void* const* d_in, const int* in_sizes, int n_in,
                              void* d_out, int out_size)
{
    // Resolve inputs by unique element count (robust to metadata ordering).
    const float* x = 0; const void* ei = 0; const float* ea = 0;
    const float* fc_w = 0; const float* fc_b = 0;
    const float* att_w = 0; const float* att_b = 0;

    int big[3] = {-1, -1, -1};
    for (int i = 0; i < n_in; i++) {
        long long s = in_sizes[i];
        if (s == 64 * 128)      { if (!fc_w) fc_w = (const float*)d_in[i]; }
        else if (s == 64 * 144) { if (!att_w) att_w = (const float*)d_in[i]; }
        else if (s == 64) {
            if (!fc_b) fc_b = (const float*)d_in[i];
            else if (!att_b) att_b = (const float*)d_in[i];
        } else {
            if (big[0] < 0) big[0] = i;
            else if (big[1] < 0) big[1] = i;
            else big[2] = i;
        }
    }
    for (int a = 0; a < 3; a++)
        for (int b = a + 1; b < 3; b++)
            if (in_sizes[big[b]] > in_sizes[big[a]]) { int tmp = big[a]; big[a] = big[b]; big[b] = tmp; }
    ea = (const float*)d_in[big[0]];
    x  = (const float*)d_in[big[1]];
    ei = d_in[big[2]];

    const int N = in_sizes[big[1]] / CDIM;   // 50000
    int E = in_sizes[big[2]] / 2;            // 800000
    if (E > E_MAX) E = E_MAX;
    float* out = (float*)d_out;

    prep_kernel<<<1184, 256>>>(ei, ea, att_w, E, N);
    int tiles = (N + 127) / 128;
    node_kernel<<<tiles, 256>>>(x, fc_w, fc_b, att_w, att_b, out, N);
    edge_kernel<<<1184, 256>>>(out, E);
}